// round 15
// baseline (speedup 1.0000x reference)
#include <cuda_runtime.h>
#include <cuda_fp16.h>
#include <cstdint>

#define NROWS 16384
#define DIM   512
#define NCODE 8192

#define LOSS_OFF   8388608
#define IDX_OFF    8388609
#define MD_OFF     8404993
#define COMMIT_OFF 8421377

// 148 CTAs: 136 x 112 rows + 12 x 96 rows = 16384. One CTA per SM (one wave).
#define NCTA  148
#define NBIG  136
#define TMBIG 112
#define TMSML 96
#define BIGROWS_END 15232            // 136*112

#define TN   256
#define NKC  8
#define NNT  (NCODE / TN)           // 32
#define TOTAL_CHUNKS (NNT * NKC)    // 256

// dynamic smem: A (max 112K) | B 3 x 32K | cand 7K | scand 3.5K | loss | mbar
#define OFF_A    0
#define OFF_B    114688
#define BSTAGE   32768
#define OFF_CAND 212992             // float2[8*112] = 7168
#define OFF_SC   220160             // int[112*8] = 3584
#define OFF_LS   223744             // float[8]
#define OFF_MB   223776             // 3 mbarriers
#define SMEM_DYN 223840

#define B_CHUNK  32768

__device__ float  g_e2[NCODE];
// chunk-major, pre-swizzled packed codebook: [nt*8+kc][rr 0..255][128B]
__device__ __half g_ch[NCODE * DIM];
__device__ float  g_partial[NCTA];

// ---------------------------------------------------------------------------
__device__ __forceinline__ uint32_t smem_u32(const void* p) {
    uint32_t a;
    asm("{ .reg .u64 t; cvta.to.shared.u64 t, %1; cvt.u32.u64 %0, t; }"
        : "=r"(a) : "l"(p));
    return a;
}
__device__ __forceinline__ void ldsm4(uint32_t* r, uint32_t addr) {
    asm volatile("ldmatrix.sync.aligned.m8n8.x4.shared.b16 {%0,%1,%2,%3}, [%4];"
                 : "=r"(r[0]), "=r"(r[1]), "=r"(r[2]), "=r"(r[3]) : "r"(addr));
}
__device__ __forceinline__ void hmma16(uint32_t* c, const uint32_t* a,
                                       uint32_t b0, uint32_t b1) {
    asm volatile(
        "mma.sync.aligned.m16n8k16.row.col.f16.f16.f16.f16 "
        "{%0,%1}, {%2,%3,%4,%5}, {%6,%7}, {%0,%1};"
        : "+r"(c[0]), "+r"(c[1])
        : "r"(a[0]), "r"(a[1]), "r"(a[2]), "r"(a[3]), "r"(b0), "r"(b1));
}
__device__ __forceinline__ void bulk_g2s(uint32_t dst, const void* src,
                                         uint32_t bytes, uint32_t mbar) {
    asm volatile(
        "cp.async.bulk.shared::cluster.global.mbarrier::complete_tx::bytes "
        "[%0], [%1], %2, [%3];"
        :: "r"(dst), "l"(src), "r"(bytes), "r"(mbar) : "memory");
}
#define MBAR_INIT(mb, c) asm volatile("mbarrier.init.shared.b64 [%0], %1;" :: "r"(mb), "r"(c) : "memory")
#define MBAR_EXPECT(mb, tx) asm volatile("mbarrier.arrive.expect_tx.shared.b64 _, [%0], %1;" :: "r"(mb), "r"(tx) : "memory")
#define MBAR_WAIT(mb, ph) do {                                              \
    uint32_t _m = (mb), _p = (ph), _d;                                      \
    asm volatile("{ .reg .pred p; mbarrier.try_wait.parity.acquire.cta.shared::cta.b64 p, [%1], %2; selp.b32 %0,1,0,p; }" \
                 : "=r"(_d) : "r"(_m), "r"(_p) : "memory");                 \
    if (!_d) {                                                              \
        asm volatile("{ .reg .pred P1;\nW%=:\n"                             \
            "mbarrier.try_wait.parity.acquire.cta.shared::cta.b64 P1, [%0], %1, 0x989680;\n" \
            "@P1 bra.uni D%=;\nbra.uni W%=;\nD%=:\n}"                       \
            :: "r"(_m), "r"(_p) : "memory");                                \
    }                                                                       \
} while (0)

// ---------------------------------------------------------------------------
// Kernel 0: codebook fp16 pack (chunk-major swizzled) + fused exact norms
// ---------------------------------------------------------------------------
__global__ void split_cb_kernel(const float* __restrict__ cb) {
    int row  = (blockIdx.x * blockDim.x + threadIdx.x) >> 5;
    int lane = threadIdx.x & 31;
    if (row >= NCODE) return;
    const float4* r4 = (const float4*)(cb + (size_t)row * DIM);
    int nt = row >> 8, rr = row & 255;

    float s = 0.f;
#pragma unroll
    for (int q = 0; q < 2; q++) {
        int gg = lane + q * 32;
        float4 v0 = r4[gg * 2];
        float4 v1 = r4[gg * 2 + 1];
        s += v0.x * v0.x + v0.y * v0.y + v0.z * v0.z + v0.w * v0.w;
        s += v1.x * v1.x + v1.y * v1.y + v1.z * v1.z + v1.w * v1.w;
        __half2 h[4];
        h[0] = __halves2half2(__float2half_rn(v0.x), __float2half_rn(v0.y));
        h[1] = __halves2half2(__float2half_rn(v0.z), __float2half_rn(v0.w));
        h[2] = __halves2half2(__float2half_rn(v1.x), __float2half_rn(v1.y));
        h[3] = __halves2half2(__float2half_rn(v1.z), __float2half_rn(v1.w));
        int kc = gg >> 3, gi = gg & 7;
        size_t off = ((size_t)(nt * 8 + kc) * 256 + rr) * 128
                   + (size_t)((gi ^ (rr & 7)) << 4);
        *(uint4*)((char*)g_ch + off) = *(uint4*)h;
    }
#pragma unroll
    for (int o = 16; o > 0; o >>= 1) s += __shfl_down_sync(0xffffffffu, s, o);
    if (lane == 0) g_e2[row] = s;
}

// ---------------------------------------------------------------------------
// Kernel 1: fused GEMM + filtered key candidates + exact refine + gather
// ---------------------------------------------------------------------------
__global__ __launch_bounds__(256, 1)
void vq_mma_kernel(const float* __restrict__ x,
                   const float* __restrict__ cb,
                   float* __restrict__ out) {
    extern __shared__ __align__(1024) char smem[];
    const uint32_t sb = smem_u32(smem);
    float2* cxf2  = (float2*)(smem + OFF_CAND);
    int*    scand = (int*)(smem + OFF_SC);
    float*  lsum  = (float*)(smem + OFF_LS);
    const uint32_t mbB0 = sb + OFF_MB;

    const int tid  = threadIdx.x;
    const int lane = tid & 31;
    const int wid  = tid >> 5;          // warp = 32-col slice
    const int blk  = blockIdx.x;

    const int ROWS    = (blk < NBIG) ? TMBIG : TMSML;
    const int MI      = (blk < NBIG) ? 7 : 6;
    const int rowbase = (blk < NBIG) ? blk * 112
                                     : BIGROWS_END + (blk - NBIG) * 96;
    const uint32_t ACH = (uint32_t)ROWS * 128;   // A chunk bytes per kc

    const int rA  = (lane & 7) + ((lane >> 3) & 1) * 8;
    const int cA  = lane >> 4;
    const int rB  = (lane & 7) + (lane >> 4) * 8;
    const int cB  = (lane >> 3) & 1;
    const int swl = lane & 7;
    const uint32_t bRow = (uint32_t)(wid * 32 + rB) * 128;
    const int g  = lane >> 2;
    const int t4 = lane & 3;

    // init running-candidate smem (top-2 keys per warp-slice per row)
    for (int idx = tid; idx < 8 * 112; idx += 256)
        cxf2[idx] = make_float2(3.4e38f, 3.4e38f);

    if (tid == 0) {
        MBAR_INIT(mbB0, 1);
        MBAR_INIT(mbB0 + 8, 1);
        MBAR_INIT(mbB0 + 16, 1);
    }
    __syncthreads();

    // B chunks 0,1,2 in flight first (3-stage)
    if (tid == 0) {
#pragma unroll
        for (int s = 0; s < 3; s++) {
            MBAR_EXPECT(mbB0 + s * 8, B_CHUNK);
            bulk_g2s(sb + OFF_B + s * BSTAGE,
                     (const char*)g_ch + (size_t)s * B_CHUNK, B_CHUNK,
                     mbB0 + s * 8);
        }
    }

    // ---- prologue: convert this CTA's fp32 rows -> swizzled fp16 A in smem ----
    {
        const float4* x4 = (const float4*)x;
        const int ngroups = ROWS * 64;
        for (int idx = tid; idx < ngroups; idx += 256) {
            int rr = idx >> 6, gg = idx & 63;
            int kc = gg >> 3, gi = gg & 7;
            float4 v0 = x4[(size_t)(rowbase + rr) * 128 + gg * 2];
            float4 v1 = x4[(size_t)(rowbase + rr) * 128 + gg * 2 + 1];
            __half2 h[4];
            h[0] = __halves2half2(__float2half_rn(v0.x), __float2half_rn(v0.y));
            h[1] = __halves2half2(__float2half_rn(v0.z), __float2half_rn(v0.w));
            h[2] = __halves2half2(__float2half_rn(v1.x), __float2half_rn(v1.y));
            h[3] = __halves2half2(__float2half_rn(v1.z), __float2half_rn(v1.w));
            uint32_t off = (uint32_t)kc * ACH + (uint32_t)rr * 128
                         + (uint32_t)((gi ^ (rr & 7)) << 4);
            *(uint4*)(smem + OFF_A + off) = *(uint4*)h;
        }
    }
    __syncthreads();   // A ready for ldsm

    // fp16x2 accumulators: [mi][nj][pair]
    uint32_t acc[7][4][2];
#pragma unroll
    for (int a = 0; a < 7; a++)
#pragma unroll
        for (int b = 0; b < 4; b++) { acc[a][b][0] = 0u; acc[a][b][1] = 0u; }

    float   e2r[8];
    __half2 e2h2[4];
    const __half2 mtwo = __floats2half2_rn(-2.f, -2.f);

#pragma unroll 1
    for (int cc = 0; cc < TOTAL_CHUNKS; cc++) {
        const int kc  = cc & 7;
        const int u3  = cc / 3;
        const int st  = cc - u3 * 3;
        const int ph  = u3 & 1;

        MBAR_WAIT(mbB0 + st * 8, ph);

        if (kc == 0) {
            const float* e2p = g_e2 + (cc >> 3) * TN + wid * 32 + 2 * t4;
#pragma unroll
            for (int j = 0; j < 4; j++) {
                e2r[j * 2]     = __ldg(e2p + j * 8);
                e2r[j * 2 + 1] = __ldg(e2p + j * 8 + 1);
                e2h2[j] = __floats2half2_rn(e2r[j * 2], e2r[j * 2 + 1]);
            }
        }

        const uint32_t stB = sb + OFF_B + (uint32_t)st * BSTAGE;
        const uint32_t stA = sb + OFF_A + (uint32_t)kc * ACH;
#pragma unroll
        for (int ks = 0; ks < 4; ks++) {
            uint32_t ah[7][4], bh[2][4];
            const uint32_t swA = (uint32_t)(((ks * 2 + cA) ^ swl) << 4);
            const uint32_t swB = (uint32_t)(((ks * 2 + cB) ^ swl) << 4);
#pragma unroll
            for (int np = 0; np < 2; np++)
                ldsm4(bh[np], stB + bRow + np * 2048 + swB);
#pragma unroll
            for (int mi = 0; mi < 7; mi++)
                if (mi < MI)
                    ldsm4(ah[mi], stA + (uint32_t)(mi * 16 + rA) * 128 + swA);
#pragma unroll
            for (int mi = 0; mi < 7; mi++)
                if (mi < MI)
#pragma unroll
                    for (int nj = 0; nj < 4; nj++)
                        hmma16(acc[mi][nj], ah[mi],
                               bh[nj >> 1][(nj & 1) * 2],
                               bh[nj >> 1][(nj & 1) * 2 + 1]);
        }

        __syncthreads();   // all warps done reading stage st
        if (tid == 0 && cc + 3 < TOTAL_CHUNKS) {
            MBAR_EXPECT(mbB0 + st * 8, B_CHUNK);
            bulk_g2s(sb + OFF_B + (uint32_t)st * BSTAGE,
                     (const char*)g_ch + (size_t)(cc + 3) * B_CHUNK,
                     B_CHUNK, mbB0 + st * 8);
        }

        if (kc == 7) {
            // ---- filtered epilogue: fp16 prefilter, exact f32 keys on hit ----
            const uint32_t colbase =
                (uint32_t)((cc >> 3) * TN + wid * 32 + 2 * t4);
#pragma unroll
            for (int mi = 0; mi < 7; mi++) {
                if (mi >= MI) continue;
#pragma unroll
                for (int p = 0; p < 2; p++) {
                    const int rowin = mi * 16 + p * 8 + g;
                    const float2 cur = cxf2[wid * 112 + rowin];
                    const __half thr1 = __float2half_rn(
                        fminf(cur.y + 8.f, 6.0e4f));
                    const __half2 thr = __halves2half2(thr1, thr1);
                    float k0 = 3.4e38f, k1 = 3.4e38f;
#pragma unroll
                    for (int nj = 0; nj < 4; nj++) {
                        __half2 a2 = *(__half2*)&acc[mi][nj][p];
                        acc[mi][nj][p] = 0u;
                        __half2 d2 = __hfma2(a2, mtwo, e2h2[nj]);
                        if (!__hbge2(d2, thr)) {
                            float2 f = __half22float2(a2);
                            float d0 = fmaf(-2.f, f.x, e2r[nj * 2]);
                            float d1 = fmaf(-2.f, f.y, e2r[nj * 2 + 1]);
                            uint32_t c0 = colbase + (uint32_t)(nj * 8);
                            float kf0 = __uint_as_float(
                                (__float_as_uint(d0) & 0xFFFFE000u) | c0);
                            float kf1 = __uint_as_float(
                                (__float_as_uint(d1) & 0xFFFFE000u) | (c0 + 1));
                            k1 = fminf(k1, fmaxf(k0, kf0));
                            k0 = fminf(k0, kf0);
                            k1 = fminf(k1, fmaxf(k0, kf1));
                            k0 = fminf(k0, kf1);
                        }
                    }
                    if (__any_sync(0xffffffffu, k0 < 3.3e38f)) {
#pragma unroll
                        for (int off = 1; off <= 2; off <<= 1) {
                            float o0 = __shfl_xor_sync(0xffffffffu, k0, off);
                            float o1 = __shfl_xor_sync(0xffffffffu, k1, off);
                            k1 = fminf(fmaxf(k0, o0), fminf(k1, o1));
                            k0 = fminf(k0, o0);
                        }
                        if (t4 == 0) {
                            float n1 = fminf(fmaxf(k0, cur.x), fminf(k1, cur.y));
                            float n0 = fminf(k0, cur.x);
                            cxf2[wid * 112 + rowin] = make_float2(n0, n1);
                        }
                    }
                }
            }
        }
    }
    __syncthreads();

    // ---- merge warp pairs (2q, 2q+1) -> top-2 per 64-col quarter -> scand ----
    if (wid < 4) {
        const int q = wid;
#pragma unroll
        for (int j = 0; j < 4; j++) {
            int row = lane + j * 32;
            if (row < ROWS) {
                float2 A = cxf2[(2 * q) * 112 + row];
                float2 B = cxf2[(2 * q + 1) * 112 + row];
                float m1 = fminf(fmaxf(A.x, B.x), fminf(A.y, B.y));
                float m0 = fminf(A.x, B.x);
                scand[row * 8 + q * 2 + 0] = __float_as_int(m0) & 0x1FFF;
                scand[row * 8 + q * 2 + 1] = __float_as_int(m1) & 0x1FFF;
            }
        }
    }
    __syncthreads();

    // ---- fused exact fp32 refine + gather + per-warp loss partial ----
    float wsum = 0.f;
    for (int r = wid; r < ROWS; r += 8) {
        const int grow = rowbase + r;
        const float4* x4 = (const float4*)(x + (size_t)grow * DIM);
        float4 xv[4];
#pragma unroll
        for (int i = 0; i < 4; i++) xv[i] = x4[lane + i * 32];

        float bv = 3.4e38f;
        int   bi = 0;
#pragma unroll
        for (int c = 0; c < 8; c++) {
            int cand = scand[r * 8 + c];
            const float4* e4 = (const float4*)(cb + (size_t)cand * DIM);
            float s = 0.f;
#pragma unroll
            for (int i = 0; i < 4; i++) {
                float4 ev = e4[lane + i * 32];
                float dx = xv[i].x - ev.x, dy = xv[i].y - ev.y;
                float dz = xv[i].z - ev.z, dw = xv[i].w - ev.w;
                s += dx * dx + dy * dy + dz * dz + dw * dw;
            }
#pragma unroll
            for (int o = 16; o > 0; o >>= 1)
                s += __shfl_xor_sync(0xffffffffu, s, o);
            if (s < bv || (s == bv && cand < bi)) { bv = s; bi = cand; }
        }
        wsum += bv;
        if (lane == 0) {
            out[IDX_OFF + grow] = (float)bi;
            out[MD_OFF + grow]  = bv;
        }
        const float4* src = (const float4*)(cb + (size_t)bi * DIM);
        float4*       dst = (float4*)(out + (size_t)grow * DIM);
#pragma unroll
        for (int i = 0; i < 4; i++) dst[lane + i * 32] = src[lane + i * 32];
    }

    // per-CTA loss partial
    if (lane == 0) lsum[wid] = wsum;
    __syncthreads();
    if (tid == 0) {
        float s = 0.f;
#pragma unroll
        for (int w = 0; w < 8; w++) s += lsum[w];
        g_partial[blk] = s;
    }
}

// ---------------------------------------------------------------------------
// Kernel 2: final deterministic loss reduction over 148 CTA partials
// ---------------------------------------------------------------------------
__global__ void vq_loss_kernel(float* __restrict__ out) {
    __shared__ float s[256];
    int t = threadIdx.x;
    s[t] = (t < NCTA) ? g_partial[t] : 0.f;
    __syncthreads();
#pragma unroll
    for (int o = 128; o > 0; o >>= 1) {
        if (t < o) s[t] += s[t + o];
        __syncthreads();
    }
    if (t == 0) {
        out[COMMIT_OFF] = s[0];
        out[LOSS_OFF]   = 1.25f * s[0];
    }
}

// ---------------------------------------------------------------------------
extern "C" void kernel_launch(void* const* d_in, const int* in_sizes, int n_in,
                              void* d_out, int out_size) {
    const float* x  = (const float*)d_in[0];   // [16384, 512]
    const float* cb = (const float*)d_in[1];   // [8192, 512]
    float* out = (float*)d_out;

    cudaFuncSetAttribute(vq_mma_kernel,
                         cudaFuncAttributeMaxDynamicSharedMemorySize, SMEM_DYN);

    split_cb_kernel<<<NCODE / 16, 512>>>(cb);
    vq_mma_kernel<<<NCTA, 256, SMEM_DYN>>>(x, cb, out);
    vq_loss_kernel<<<1, 256>>>(out);
}

// round 16
// speedup vs baseline: 1.1644x; 1.1644x over previous
#include <cuda_runtime.h>
#include <cuda_fp16.h>
#include <cstdint>

#define NROWS 16384
#define DIM   512
#define NCODE 8192

#define LOSS_OFF   8388608
#define IDX_OFF    8388609
#define MD_OFF     8404993
#define COMMIT_OFF 8421377

// 148 CTAs: 136 x 112 rows + 12 x 96 rows = 16384. One CTA per SM (one wave).
#define NCTA  148
#define NBIG  136
#define TMBIG 112
#define TMSML 96
#define BIGROWS_END 15232            // 136*112

#define TN   256
#define NKC  8
#define NNT  (NCODE / TN)           // 32
#define TOTAL_CHUNKS (NNT * NKC)    // 256

// dynamic smem: A (max 112K) | B 2 x 32K | cand 7K | scand 3.5K | loss | mbar
#define OFF_A    0
#define OFF_B    114688
#define BSTAGE   32768
#define OFF_CAND 180224             // float2[8*112] = 7168
#define OFF_SC   187392             // int[112*8] = 3584
#define OFF_LS   190976             // float[8]
#define OFF_MB   191040             // full0,full1,empty0,empty1
#define SMEM_DYN 191104

#define B_CHUNK  32768

__device__ float  g_e2[NCODE];
// chunk-major, pre-swizzled packed codebook: [nt*8+kc][rr 0..255][128B]
__device__ __half g_ch[NCODE * DIM];
__device__ float  g_partial[NCTA];

// ---------------------------------------------------------------------------
__device__ __forceinline__ uint32_t smem_u32(const void* p) {
    uint32_t a;
    asm("{ .reg .u64 t; cvta.to.shared.u64 t, %1; cvt.u32.u64 %0, t; }"
        : "=r"(a) : "l"(p));
    return a;
}
__device__ __forceinline__ void ldsm4(uint32_t* r, uint32_t addr) {
    asm volatile("ldmatrix.sync.aligned.m8n8.x4.shared.b16 {%0,%1,%2,%3}, [%4];"
                 : "=r"(r[0]), "=r"(r[1]), "=r"(r[2]), "=r"(r[3]) : "r"(addr));
}
__device__ __forceinline__ void hmma16(uint32_t* c, const uint32_t* a,
                                       uint32_t b0, uint32_t b1) {
    asm volatile(
        "mma.sync.aligned.m16n8k16.row.col.f16.f16.f16.f16 "
        "{%0,%1}, {%2,%3,%4,%5}, {%6,%7}, {%0,%1};"
        : "+r"(c[0]), "+r"(c[1])
        : "r"(a[0]), "r"(a[1]), "r"(a[2]), "r"(a[3]), "r"(b0), "r"(b1));
}
__device__ __forceinline__ void bulk_g2s(uint32_t dst, const void* src,
                                         uint32_t bytes, uint32_t mbar) {
    asm volatile(
        "cp.async.bulk.shared::cluster.global.mbarrier::complete_tx::bytes "
        "[%0], [%1], %2, [%3];"
        :: "r"(dst), "l"(src), "r"(bytes), "r"(mbar) : "memory");
}
#define MBAR_INIT(mb, c) asm volatile("mbarrier.init.shared.b64 [%0], %1;" :: "r"(mb), "r"(c) : "memory")
#define MBAR_EXPECT(mb, tx) asm volatile("mbarrier.arrive.expect_tx.shared.b64 _, [%0], %1;" :: "r"(mb), "r"(tx) : "memory")
#define MBAR_ARRIVE(mb) asm volatile("mbarrier.arrive.release.cta.shared.b64 _, [%0];" :: "r"(mb) : "memory")
#define MBAR_WAIT(mb, ph) do {                                              \
    uint32_t _m = (mb), _p = (ph), _d;                                      \
    asm volatile("{ .reg .pred p; mbarrier.try_wait.parity.acquire.cta.shared::cta.b64 p, [%1], %2; selp.b32 %0,1,0,p; }" \
                 : "=r"(_d) : "r"(_m), "r"(_p) : "memory");                 \
    if (!_d) {                                                              \
        asm volatile("{ .reg .pred P1;\nW%=:\n"                             \
            "mbarrier.try_wait.parity.acquire.cta.shared::cta.b64 P1, [%0], %1, 0x989680;\n" \
            "@P1 bra.uni D%=;\nbra.uni W%=;\nD%=:\n}"                       \
            :: "r"(_m), "r"(_p) : "memory");                                \
    }                                                                       \
} while (0)

// ---------------------------------------------------------------------------
// Kernel 0: codebook fp16 pack (chunk-major swizzled) + fused exact norms
// ---------------------------------------------------------------------------
__global__ void split_cb_kernel(const float* __restrict__ cb) {
    int row  = (blockIdx.x * blockDim.x + threadIdx.x) >> 5;
    int lane = threadIdx.x & 31;
    if (row >= NCODE) return;
    const float4* r4 = (const float4*)(cb + (size_t)row * DIM);
    int nt = row >> 8, rr = row & 255;

    float s = 0.f;
#pragma unroll
    for (int q = 0; q < 2; q++) {
        int gg = lane + q * 32;
        float4 v0 = r4[gg * 2];
        float4 v1 = r4[gg * 2 + 1];
        s += v0.x * v0.x + v0.y * v0.y + v0.z * v0.z + v0.w * v0.w;
        s += v1.x * v1.x + v1.y * v1.y + v1.z * v1.z + v1.w * v1.w;
        __half2 h[4];
        h[0] = __halves2half2(__float2half_rn(v0.x), __float2half_rn(v0.y));
        h[1] = __halves2half2(__float2half_rn(v0.z), __float2half_rn(v0.w));
        h[2] = __halves2half2(__float2half_rn(v1.x), __float2half_rn(v1.y));
        h[3] = __halves2half2(__float2half_rn(v1.z), __float2half_rn(v1.w));
        int kc = gg >> 3, gi = gg & 7;
        size_t off = ((size_t)(nt * 8 + kc) * 256 + rr) * 128
                   + (size_t)((gi ^ (rr & 7)) << 4);
        *(uint4*)((char*)g_ch + off) = *(uint4*)h;
    }
#pragma unroll
    for (int o = 16; o > 0; o >>= 1) s += __shfl_down_sync(0xffffffffu, s, o);
    if (lane == 0) g_e2[row] = s;
}

// ---------------------------------------------------------------------------
// Kernel 1: fused GEMM + key-based candidates + exact refine + gather + loss
//           producer/consumer mbarriers, no per-chunk block barrier.
// ---------------------------------------------------------------------------
__global__ __launch_bounds__(256, 1)
void vq_mma_kernel(const float* __restrict__ x,
                   const float* __restrict__ cb,
                   float* __restrict__ out) {
    extern __shared__ __align__(1024) char smem[];
    const uint32_t sb = smem_u32(smem);
    float2* cxf2  = (float2*)(smem + OFF_CAND);
    int*    scand = (int*)(smem + OFF_SC);
    float*  lsum  = (float*)(smem + OFF_LS);
    const uint32_t mbF = sb + OFF_MB;        // full0, full1
    const uint32_t mbE = sb + OFF_MB + 16;   // empty0, empty1

    const int tid  = threadIdx.x;
    const int lane = tid & 31;
    const int wid  = tid >> 5;          // warp = 32-col slice
    const int blk  = blockIdx.x;

    const int ROWS    = (blk < NBIG) ? TMBIG : TMSML;
    const int MI      = (blk < NBIG) ? 7 : 6;
    const int rowbase = (blk < NBIG) ? blk * 112
                                     : BIGROWS_END + (blk - NBIG) * 96;
    const uint32_t ACH = (uint32_t)ROWS * 128;   // A chunk bytes per kc

    const int rA  = (lane & 7) + ((lane >> 3) & 1) * 8;
    const int cA  = lane >> 4;
    const int rB  = (lane & 7) + (lane >> 4) * 8;
    const int cB  = (lane >> 3) & 1;
    const int swl = lane & 7;
    const uint32_t bRow = (uint32_t)(wid * 32 + rB) * 128;
    const int g  = lane >> 2;
    const int t4 = lane & 3;

    // init running-candidate smem (top-2 keys per warp-slice per row)
    for (int idx = tid; idx < 8 * 112; idx += 256)
        cxf2[idx] = make_float2(3.4e38f, 3.4e38f);

    if (tid == 0) {
        MBAR_INIT(mbF, 1);
        MBAR_INIT(mbF + 8, 1);
        MBAR_INIT(mbE, 8);
        MBAR_INIT(mbE + 8, 8);
    }
    __syncthreads();

    // B chunks 0,1 in flight first
    if (tid == 0) {
        MBAR_EXPECT(mbF, B_CHUNK);
        bulk_g2s(sb + OFF_B, (const char*)g_ch, B_CHUNK, mbF);
        MBAR_EXPECT(mbF + 8, B_CHUNK);
        bulk_g2s(sb + OFF_B + BSTAGE, (const char*)g_ch + B_CHUNK, B_CHUNK, mbF + 8);
    }

    // ---- prologue: convert this CTA's fp32 rows -> swizzled fp16 A in smem ----
    {
        const float4* x4 = (const float4*)x;
        const int ngroups = ROWS * 64;
        for (int idx = tid; idx < ngroups; idx += 256) {
            int rr = idx >> 6, gg = idx & 63;
            int kc = gg >> 3, gi = gg & 7;
            float4 v0 = x4[(size_t)(rowbase + rr) * 128 + gg * 2];
            float4 v1 = x4[(size_t)(rowbase + rr) * 128 + gg * 2 + 1];
            __half2 h[4];
            h[0] = __halves2half2(__float2half_rn(v0.x), __float2half_rn(v0.y));
            h[1] = __halves2half2(__float2half_rn(v0.z), __float2half_rn(v0.w));
            h[2] = __halves2half2(__float2half_rn(v1.x), __float2half_rn(v1.y));
            h[3] = __halves2half2(__float2half_rn(v1.z), __float2half_rn(v1.w));
            uint32_t off = (uint32_t)kc * ACH + (uint32_t)rr * 128
                         + (uint32_t)((gi ^ (rr & 7)) << 4);
            *(uint4*)(smem + OFF_A + off) = *(uint4*)h;
        }
    }
    __syncthreads();   // A ready for ldsm

    // fp16x2 accumulators: [mi][nj][pair]
    uint32_t acc[7][4][2];
#pragma unroll
    for (int a = 0; a < 7; a++)
#pragma unroll
        for (int b = 0; b < 4; b++) { acc[a][b][0] = 0u; acc[a][b][1] = 0u; }

    float e2r[8];

#pragma unroll 1
    for (int cc = 0; cc < TOTAL_CHUNKS; cc++) {
        const int kc  = cc & 7;
        const int stg = cc & 1;
        const int ph  = (cc >> 1) & 1;

        MBAR_WAIT(mbF + stg * 8, ph);

        if (kc == 0) {
            const float* e2p = g_e2 + (cc >> 3) * TN + wid * 32 + 2 * t4;
#pragma unroll
            for (int j = 0; j < 4; j++) {
                e2r[j * 2]     = __ldg(e2p + j * 8);
                e2r[j * 2 + 1] = __ldg(e2p + j * 8 + 1);
            }
        }

        const uint32_t stB = sb + OFF_B + (uint32_t)stg * BSTAGE;
        const uint32_t stA = sb + OFF_A + (uint32_t)kc * ACH;
#pragma unroll
        for (int ks = 0; ks < 4; ks++) {
            uint32_t ah[7][4], bh[2][4];
            const uint32_t swA = (uint32_t)(((ks * 2 + cA) ^ swl) << 4);
            const uint32_t swB = (uint32_t)(((ks * 2 + cB) ^ swl) << 4);
#pragma unroll
            for (int np = 0; np < 2; np++)
                ldsm4(bh[np], stB + bRow + np * 2048 + swB);
#pragma unroll
            for (int mi = 0; mi < 7; mi++)
                if (mi < MI)
                    ldsm4(ah[mi], stA + (uint32_t)(mi * 16 + rA) * 128 + swA);
#pragma unroll
            for (int mi = 0; mi < 7; mi++)
                if (mi < MI)
#pragma unroll
                    for (int nj = 0; nj < 4; nj++)
                        hmma16(acc[mi][nj], ah[mi],
                               bh[nj >> 1][(nj & 1) * 2],
                               bh[nj >> 1][(nj & 1) * 2 + 1]);
        }

        // this warp is done reading stage stg for this chunk
        if (lane == 0) MBAR_ARRIVE(mbE + stg * 8);

        // producer: wait all 8 warps done with stage stg, then refill it
        if (tid == 0 && cc + 2 < TOTAL_CHUNKS) {
            MBAR_WAIT(mbE + stg * 8, ph);
            MBAR_EXPECT(mbF + stg * 8, B_CHUNK);
            bulk_g2s(sb + OFF_B + (uint32_t)stg * BSTAGE,
                     (const char*)g_ch + (size_t)(cc + 2) * B_CHUNK,
                     B_CHUNK, mbF + stg * 8);
        }

        if (kc == 7) {
            // ---- epilogue: top-2 keys (index in low 13 mantissa bits) ----
            const uint32_t colbase =
                (uint32_t)((cc >> 3) * TN + wid * 32 + 2 * t4);
#pragma unroll
            for (int mi = 0; mi < 7; mi++) {
                if (mi >= MI) continue;
#pragma unroll
                for (int p = 0; p < 2; p++) {
                    float k0 = 3.4e38f, k1 = 3.4e38f;
#pragma unroll
                    for (int nj = 0; nj < 4; nj++) {
                        float2 f = __half22float2(*(__half2*)&acc[mi][nj][p]);
                        acc[mi][nj][p] = 0u;
#pragma unroll
                        for (int c = 0; c < 2; c++) {
                            float d = fmaf(-2.f, (c == 0) ? f.x : f.y,
                                           e2r[nj * 2 + c]);
                            uint32_t kb = (__float_as_uint(d) & 0xFFFFE000u)
                                        | (colbase + (uint32_t)(nj * 8 + c));
                            float kf = __uint_as_float(kb);
                            k1 = fminf(k1, fmaxf(k0, kf));
                            k0 = fminf(k0, kf);
                        }
                    }
#pragma unroll
                    for (int off = 1; off <= 2; off <<= 1) {
                        float o0 = __shfl_xor_sync(0xffffffffu, k0, off);
                        float o1 = __shfl_xor_sync(0xffffffffu, k1, off);
                        k1 = fminf(fmaxf(k0, o0), fminf(k1, o1));
                        k0 = fminf(k0, o0);
                    }
                    if (t4 == 0) {
                        int rowin = mi * 16 + p * 8 + g;
                        float2 cur = cxf2[wid * 112 + rowin];
                        float n1 = fminf(fmaxf(k0, cur.x), fminf(k1, cur.y));
                        float n0 = fminf(k0, cur.x);
                        cxf2[wid * 112 + rowin] = make_float2(n0, n1);
                    }
                }
            }
        }
    }
    __syncthreads();

    // ---- merge warp pairs (2q, 2q+1) -> top-2 per 64-col quarter -> scand ----
    if (wid < 4) {
        const int q = wid;
#pragma unroll
        for (int j = 0; j < 4; j++) {
            int row = lane + j * 32;
            if (row < ROWS) {
                float2 A = cxf2[(2 * q) * 112 + row];
                float2 B = cxf2[(2 * q + 1) * 112 + row];
                float m1 = fminf(fmaxf(A.x, B.x), fminf(A.y, B.y));
                float m0 = fminf(A.x, B.x);
                scand[row * 8 + q * 2 + 0] = __float_as_int(m0) & 0x1FFF;
                scand[row * 8 + q * 2 + 1] = __float_as_int(m1) & 0x1FFF;
            }
        }
    }
    __syncthreads();

    // ---- fused exact fp32 refine + gather + per-warp loss partial ----
    float wsum = 0.f;
    for (int r = wid; r < ROWS; r += 8) {
        const int grow = rowbase + r;
        const float4* x4 = (const float4*)(x + (size_t)grow * DIM);
        float4 xv[4];
#pragma unroll
        for (int i = 0; i < 4; i++) xv[i] = x4[lane + i * 32];

        float bv = 3.4e38f;
        int   bi = 0;
#pragma unroll
        for (int c = 0; c < 8; c++) {
            int cand = scand[r * 8 + c];
            const float4* e4 = (const float4*)(cb + (size_t)cand * DIM);
            float s = 0.f;
#pragma unroll
            for (int i = 0; i < 4; i++) {
                float4 ev = e4[lane + i * 32];
                float dx = xv[i].x - ev.x, dy = xv[i].y - ev.y;
                float dz = xv[i].z - ev.z, dw = xv[i].w - ev.w;
                s += dx * dx + dy * dy + dz * dz + dw * dw;
            }
#pragma unroll
            for (int o = 16; o > 0; o >>= 1)
                s += __shfl_xor_sync(0xffffffffu, s, o);
            if (s < bv || (s == bv && cand < bi)) { bv = s; bi = cand; }
        }
        wsum += bv;
        if (lane == 0) {
            out[IDX_OFF + grow] = (float)bi;
            out[MD_OFF + grow]  = bv;
        }
        const float4* src = (const float4*)(cb + (size_t)bi * DIM);
        float4*       dst = (float4*)(out + (size_t)grow * DIM);
#pragma unroll
        for (int i = 0; i < 4; i++) dst[lane + i * 32] = src[lane + i * 32];
    }

    // per-CTA loss partial
    if (lane == 0) lsum[wid] = wsum;
    __syncthreads();
    if (tid == 0) {
        float s = 0.f;
#pragma unroll
        for (int w = 0; w < 8; w++) s += lsum[w];
        g_partial[blk] = s;
    }
}

// ---------------------------------------------------------------------------
// Kernel 2: final deterministic loss reduction over 148 CTA partials
// ---------------------------------------------------------------------------
__global__ void vq_loss_kernel(float* __restrict__ out) {
    __shared__ float s[256];
    int t = threadIdx.x;
    s[t] = (t < NCTA) ? g_partial[t] : 0.f;
    __syncthreads();
#pragma unroll
    for (int o = 128; o > 0; o >>= 1) {
        if (t < o) s[t] += s[t + o];
        __syncthreads();
    }
    if (t == 0) {
        out[COMMIT_OFF] = s[0];
        out[LOSS_OFF]   = 1.25f * s[0];
    }
}

// ---------------------------------------------------------------------------
extern "C" void kernel_launch(void* const* d_in, const int* in_sizes, int n_in,
                              void* d_out, int out_size) {
    const float* x  = (const float*)d_in[0];   // [16384, 512]
    const float* cb = (const float*)d_in[1];   // [8192, 512]
    float* out = (float*)d_out;

    cudaFuncSetAttribute(vq_mma_kernel,
                         cudaFuncAttributeMaxDynamicSharedMemorySize, SMEM_DYN);

    split_cb_kernel<<<NCODE / 16, 512>>>(cb);
    vq_mma_kernel<<<NCTA, 256, SMEM_DYN>>>(x, cb, out);
    vq_loss_kernel<<<1, 256>>>(out);
}

// round 17
// speedup vs baseline: 1.2354x; 1.0610x over previous
#include <cuda_runtime.h>
#include <cuda_fp16.h>
#include <cstdint>

#define NROWS 16384
#define DIM   512
#define NCODE 8192

#define LOSS_OFF   8388608
#define IDX_OFF    8388609
#define MD_OFF     8404993
#define COMMIT_OFF 8421377

// 148 CTAs: 136 x 112 rows + 12 x 96 rows = 16384. One CTA per SM (one wave).
#define NCTA  148
#define NBIG  136
#define TMBIG 112
#define TMSML 96
#define BIGROWS_END 15232            // 136*112

#define TN   256
#define NKC  8
#define NNT  (NCODE / TN)           // 32
#define TOTAL_CHUNKS (NNT * NKC)    // 256

// dynamic smem: A (max 112K) | B 2 x 32K | cand 7K | scand 3.5K | loss | mbar
#define OFF_A    0
#define OFF_B    114688
#define BSTAGE   32768
#define OFF_CAND 180224             // float2[8*112] = 7168
#define OFF_SC   187392             // int[112*8] = 3584
#define OFF_LS   190976             // float[8]
#define OFF_MB   191040             // full0,full1,empty0,empty1
#define SMEM_DYN 191104

#define B_CHUNK  32768

__device__ float  g_e2[NCODE];
// chunk-major, pre-swizzled packed codebook: [nt*8+kc][rr 0..255][128B]
__device__ __half g_ch[NCODE * DIM];
__device__ float  g_partial[NCTA];

// ---------------------------------------------------------------------------
__device__ __forceinline__ uint32_t smem_u32(const void* p) {
    uint32_t a;
    asm("{ .reg .u64 t; cvta.to.shared.u64 t, %1; cvt.u32.u64 %0, t; }"
        : "=r"(a) : "l"(p));
    return a;
}
__device__ __forceinline__ void ldsm4(uint32_t* r, uint32_t addr) {
    asm volatile("ldmatrix.sync.aligned.m8n8.x4.shared.b16 {%0,%1,%2,%3}, [%4];"
                 : "=r"(r[0]), "=r"(r[1]), "=r"(r[2]), "=r"(r[3]) : "r"(addr));
}
__device__ __forceinline__ void hmma16(uint32_t* c, const uint32_t* a,
                                       uint32_t b0, uint32_t b1) {
    asm volatile(
        "mma.sync.aligned.m16n8k16.row.col.f16.f16.f16.f16 "
        "{%0,%1}, {%2,%3,%4,%5}, {%6,%7}, {%0,%1};"
        : "+r"(c[0]), "+r"(c[1])
        : "r"(a[0]), "r"(a[1]), "r"(a[2]), "r"(a[3]), "r"(b0), "r"(b1));
}
__device__ __forceinline__ void bulk_g2s(uint32_t dst, const void* src,
                                         uint32_t bytes, uint32_t mbar) {
    asm volatile(
        "cp.async.bulk.shared::cluster.global.mbarrier::complete_tx::bytes "
        "[%0], [%1], %2, [%3];"
        :: "r"(dst), "l"(src), "r"(bytes), "r"(mbar) : "memory");
}
#define MBAR_INIT(mb, c) asm volatile("mbarrier.init.shared.b64 [%0], %1;" :: "r"(mb), "r"(c) : "memory")
#define MBAR_EXPECT(mb, tx) asm volatile("mbarrier.arrive.expect_tx.shared.b64 _, [%0], %1;" :: "r"(mb), "r"(tx) : "memory")
#define MBAR_ARRIVE(mb) asm volatile("mbarrier.arrive.release.cta.shared.b64 _, [%0];" :: "r"(mb) : "memory")
#define MBAR_WAIT(mb, ph) do {                                              \
    uint32_t _m = (mb), _p = (ph), _d;                                      \
    asm volatile("{ .reg .pred p; mbarrier.try_wait.parity.acquire.cta.shared::cta.b64 p, [%1], %2; selp.b32 %0,1,0,p; }" \
                 : "=r"(_d) : "r"(_m), "r"(_p) : "memory");                 \
    if (!_d) {                                                              \
        asm volatile("{ .reg .pred P1;\nW%=:\n"                             \
            "mbarrier.try_wait.parity.acquire.cta.shared::cta.b64 P1, [%0], %1, 0x989680;\n" \
            "@P1 bra.uni D%=;\nbra.uni W%=;\nD%=:\n}"                       \
            :: "r"(_m), "r"(_p) : "memory");                                \
    }                                                                       \
} while (0)

// ---------------------------------------------------------------------------
// Kernel 0: codebook fp16 pack (chunk-major swizzled) + fused exact norms
// ---------------------------------------------------------------------------
__global__ void split_cb_kernel(const float* __restrict__ cb) {
    int row  = (blockIdx.x * blockDim.x + threadIdx.x) >> 5;
    int lane = threadIdx.x & 31;
    if (row >= NCODE) return;
    const float4* r4 = (const float4*)(cb + (size_t)row * DIM);
    int nt = row >> 8, rr = row & 255;

    float s = 0.f;
#pragma unroll
    for (int q = 0; q < 2; q++) {
        int gg = lane + q * 32;
        float4 v0 = r4[gg * 2];
        float4 v1 = r4[gg * 2 + 1];
        s += v0.x * v0.x + v0.y * v0.y + v0.z * v0.z + v0.w * v0.w;
        s += v1.x * v1.x + v1.y * v1.y + v1.z * v1.z + v1.w * v1.w;
        __half2 h[4];
        h[0] = __halves2half2(__float2half_rn(v0.x), __float2half_rn(v0.y));
        h[1] = __halves2half2(__float2half_rn(v0.z), __float2half_rn(v0.w));
        h[2] = __halves2half2(__float2half_rn(v1.x), __float2half_rn(v1.y));
        h[3] = __halves2half2(__float2half_rn(v1.z), __float2half_rn(v1.w));
        int kc = gg >> 3, gi = gg & 7;
        size_t off = ((size_t)(nt * 8 + kc) * 256 + rr) * 128
                   + (size_t)((gi ^ (rr & 7)) << 4);
        *(uint4*)((char*)g_ch + off) = *(uint4*)h;
    }
#pragma unroll
    for (int o = 16; o > 0; o >>= 1) s += __shfl_down_sync(0xffffffffu, s, o);
    if (lane == 0) g_e2[row] = s;
}

// ---------------------------------------------------------------------------
// Kernel 1: fused GEMM, ping-pong accumulators with spread epilogue,
//           mbarrier pipeline, exact refine + gather + loss partials.
// ---------------------------------------------------------------------------
__global__ __launch_bounds__(256, 1)
void vq_mma_kernel(const float* __restrict__ x,
                   const float* __restrict__ cb,
                   float* __restrict__ out) {
    extern __shared__ __align__(1024) char smem[];
    const uint32_t sb = smem_u32(smem);
    float2* cxf2  = (float2*)(smem + OFF_CAND);
    int*    scand = (int*)(smem + OFF_SC);
    float*  lsum  = (float*)(smem + OFF_LS);
    const uint32_t mbF = sb + OFF_MB;        // full0, full1
    const uint32_t mbE = sb + OFF_MB + 16;   // empty0, empty1

    const int tid  = threadIdx.x;
    const int lane = tid & 31;
    const int wid  = tid >> 5;          // warp = 32-col slice
    const int blk  = blockIdx.x;

    const int ROWS    = (blk < NBIG) ? TMBIG : TMSML;
    const int MI      = (blk < NBIG) ? 7 : 6;
    const int rowbase = (blk < NBIG) ? blk * 112
                                     : BIGROWS_END + (blk - NBIG) * 96;
    const uint32_t ACH = (uint32_t)ROWS * 128;   // A chunk bytes per kc

    const int rA  = (lane & 7) + ((lane >> 3) & 1) * 8;
    const int cA  = lane >> 4;
    const int rB  = (lane & 7) + (lane >> 4) * 8;
    const int cB  = (lane >> 3) & 1;
    const int swl = lane & 7;
    const uint32_t bRow = (uint32_t)(wid * 32 + rB) * 128;
    const int g  = lane >> 2;
    const int t4 = lane & 3;

    // init running-candidate smem (top-2 keys per warp-slice per row)
    for (int idx = tid; idx < 8 * 112; idx += 256)
        cxf2[idx] = make_float2(3.4e38f, 3.4e38f);

    if (tid == 0) {
        MBAR_INIT(mbF, 1);
        MBAR_INIT(mbF + 8, 1);
        MBAR_INIT(mbE, 8);
        MBAR_INIT(mbE + 8, 8);
    }
    __syncthreads();

    // B chunks 0,1 in flight first
    if (tid == 0) {
        MBAR_EXPECT(mbF, B_CHUNK);
        bulk_g2s(sb + OFF_B, (const char*)g_ch, B_CHUNK, mbF);
        MBAR_EXPECT(mbF + 8, B_CHUNK);
        bulk_g2s(sb + OFF_B + BSTAGE, (const char*)g_ch + B_CHUNK, B_CHUNK, mbF + 8);
    }

    // ---- prologue: convert this CTA's fp32 rows -> swizzled fp16 A in smem ----
    {
        const float4* x4 = (const float4*)x;
        const int ngroups = ROWS * 64;
        for (int idx = tid; idx < ngroups; idx += 256) {
            int rr = idx >> 6, gg = idx & 63;
            int kc = gg >> 3, gi = gg & 7;
            float4 v0 = x4[(size_t)(rowbase + rr) * 128 + gg * 2];
            float4 v1 = x4[(size_t)(rowbase + rr) * 128 + gg * 2 + 1];
            __half2 h[4];
            h[0] = __halves2half2(__float2half_rn(v0.x), __float2half_rn(v0.y));
            h[1] = __halves2half2(__float2half_rn(v0.z), __float2half_rn(v0.w));
            h[2] = __halves2half2(__float2half_rn(v1.x), __float2half_rn(v1.y));
            h[3] = __halves2half2(__float2half_rn(v1.z), __float2half_rn(v1.w));
            uint32_t off = (uint32_t)kc * ACH + (uint32_t)rr * 128
                         + (uint32_t)((gi ^ (rr & 7)) << 4);
            *(uint4*)(smem + OFF_A + off) = *(uint4*)h;
        }
    }
    __syncthreads();   // A ready for ldsm

    // ping-pong fp16x2 accumulators
    uint32_t accA[7][4][2], accB[7][4][2];
#pragma unroll
    for (int a = 0; a < 7; a++)
#pragma unroll
        for (int b = 0; b < 4; b++) {
            accA[a][b][0] = 0u; accA[a][b][1] = 0u;
            accB[a][b][0] = 0u; accB[a][b][1] = 0u;
        }
    float e2rA[8], e2rB[8];

    // epilogue for one mi-slot of the PREVIOUS tile (keys: idx in mantissa)
    auto epi_mi = [&](uint32_t (&A)[7][4][2], float (&E)[8], int mi,
                      uint32_t colbase) {
#pragma unroll
        for (int p = 0; p < 2; p++) {
            float k0 = 3.4e38f, k1 = 3.4e38f;
#pragma unroll
            for (int nj = 0; nj < 4; nj++) {
                float2 f = __half22float2(*(__half2*)&A[mi][nj][p]);
                A[mi][nj][p] = 0u;
#pragma unroll
                for (int c = 0; c < 2; c++) {
                    float d = fmaf(-2.f, (c == 0) ? f.x : f.y,
                                   E[nj * 2 + c]);
                    uint32_t kb = (__float_as_uint(d) & 0xFFFFE000u)
                                | (colbase + (uint32_t)(nj * 8 + c));
                    float kf = __uint_as_float(kb);
                    k1 = fminf(k1, fmaxf(k0, kf));
                    k0 = fminf(k0, kf);
                }
            }
#pragma unroll
            for (int off = 1; off <= 2; off <<= 1) {
                float o0 = __shfl_xor_sync(0xffffffffu, k0, off);
                float o1 = __shfl_xor_sync(0xffffffffu, k1, off);
                k1 = fminf(fmaxf(k0, o0), fminf(k1, o1));
                k0 = fminf(k0, o0);
            }
            if (t4 == 0) {
                int rowin = mi * 16 + p * 8 + g;
                float2 cur = cxf2[wid * 112 + rowin];
                float n1 = fminf(fmaxf(k0, cur.x), fminf(k1, cur.y));
                float n0 = fminf(k0, cur.x);
                cxf2[wid * 112 + rowin] = make_float2(n0, n1);
            }
        }
    };

    // one n-tile: MMA into accC, spread epilogue of accP (mi = kc, kc 0..6)
    auto run_tile = [&](uint32_t (&accC)[7][4][2], uint32_t (&accP)[7][4][2],
                        float (&e2C)[8], float (&e2P)[8], int nt, bool do_epi) {
#pragma unroll
        for (int kc = 0; kc < 8; kc++) {
            const int cc  = nt * 8 + kc;
            const int stg = kc & 1;
            const int ph  = (kc >> 1) & 1;   // == (cc>>1)&1 since 8nt>>1 even

            MBAR_WAIT(mbF + stg * 8, ph);

            if (kc == 0) {
                const float* e2p = g_e2 + nt * TN + wid * 32 + 2 * t4;
#pragma unroll
                for (int j = 0; j < 4; j++) {
                    e2C[j * 2]     = __ldg(e2p + j * 8);
                    e2C[j * 2 + 1] = __ldg(e2p + j * 8 + 1);
                }
            }

            const uint32_t stB = sb + OFF_B + (uint32_t)stg * BSTAGE;
            const uint32_t stA = sb + OFF_A + (uint32_t)kc * ACH;
#pragma unroll
            for (int ks = 0; ks < 4; ks++) {
                uint32_t ah[7][4], bh[2][4];
                const uint32_t swA = (uint32_t)(((ks * 2 + cA) ^ swl) << 4);
                const uint32_t swB = (uint32_t)(((ks * 2 + cB) ^ swl) << 4);
#pragma unroll
                for (int np = 0; np < 2; np++)
                    ldsm4(bh[np], stB + bRow + np * 2048 + swB);
#pragma unroll
                for (int mi = 0; mi < 7; mi++)
                    if (mi < MI)
                        ldsm4(ah[mi], stA + (uint32_t)(mi * 16 + rA) * 128 + swA);
#pragma unroll
                for (int mi = 0; mi < 7; mi++)
                    if (mi < MI)
#pragma unroll
                        for (int nj = 0; nj < 4; nj++)
                            hmma16(accC[mi][nj], ah[mi],
                                   bh[nj >> 1][(nj & 1) * 2],
                                   bh[nj >> 1][(nj & 1) * 2 + 1]);
            }

            if (lane == 0) MBAR_ARRIVE(mbE + stg * 8);
            if (tid == 0 && cc + 2 < TOTAL_CHUNKS) {
                MBAR_WAIT(mbE + stg * 8, ph);
                MBAR_EXPECT(mbF + stg * 8, B_CHUNK);
                bulk_g2s(sb + OFF_B + (uint32_t)stg * BSTAGE,
                         (const char*)g_ch + (size_t)(cc + 2) * B_CHUNK,
                         B_CHUNK, mbF + stg * 8);
            }

            // spread epilogue: slot mi = kc of the previous tile
            if (do_epi && kc < 7 && kc < MI) {
                const uint32_t colbase =
                    (uint32_t)((nt - 1) * TN + wid * 32 + 2 * t4);
                epi_mi(accP, e2P, kc, colbase);
            }
        }
    };

#pragma unroll 1
    for (int nt = 0; nt < NNT; nt += 2) {
        run_tile(accA, accB, e2rA, e2rB, nt, nt > 0);
        run_tile(accB, accA, e2rB, e2rA, nt + 1, true);
    }
    // final epilogue: tile 31 lives in accB
    {
        const uint32_t colbase =
            (uint32_t)((NNT - 1) * TN + wid * 32 + 2 * t4);
#pragma unroll
        for (int mi = 0; mi < 7; mi++)
            if (mi < MI) epi_mi(accB, e2rB, mi, colbase);
    }
    __syncthreads();

    // ---- merge warp pairs (2q, 2q+1) -> top-2 per 64-col quarter -> scand ----
    if (wid < 4) {
        const int q = wid;
#pragma unroll
        for (int j = 0; j < 4; j++) {
            int row = lane + j * 32;
            if (row < ROWS) {
                float2 A = cxf2[(2 * q) * 112 + row];
                float2 B = cxf2[(2 * q + 1) * 112 + row];
                float m1 = fminf(fmaxf(A.x, B.x), fminf(A.y, B.y));
                float m0 = fminf(A.x, B.x);
                scand[row * 8 + q * 2 + 0] = __float_as_int(m0) & 0x1FFF;
                scand[row * 8 + q * 2 + 1] = __float_as_int(m1) & 0x1FFF;
            }
        }
    }
    __syncthreads();

    // ---- fused exact fp32 refine + gather + per-warp loss partial ----
    float wsum = 0.f;
    for (int r = wid; r < ROWS; r += 8) {
        const int grow = rowbase + r;
        const float4* x4 = (const float4*)(x + (size_t)grow * DIM);
        float4 xv[4];
#pragma unroll
        for (int i = 0; i < 4; i++) xv[i] = x4[lane + i * 32];

        float bv = 3.4e38f;
        int   bi = 0;
#pragma unroll
        for (int c = 0; c < 8; c++) {
            int cand = scand[r * 8 + c];
            const float4* e4 = (const float4*)(cb + (size_t)cand * DIM);
            float s = 0.f;
#pragma unroll
            for (int i = 0; i < 4; i++) {
                float4 ev = e4[lane + i * 32];
                float dx = xv[i].x - ev.x, dy = xv[i].y - ev.y;
                float dz = xv[i].z - ev.z, dw = xv[i].w - ev.w;
                s += dx * dx + dy * dy + dz * dz + dw * dw;
            }
#pragma unroll
            for (int o = 16; o > 0; o >>= 1)
                s += __shfl_xor_sync(0xffffffffu, s, o);
            if (s < bv || (s == bv && cand < bi)) { bv = s; bi = cand; }
        }
        wsum += bv;
        if (lane == 0) {
            out[IDX_OFF + grow] = (float)bi;
            out[MD_OFF + grow]  = bv;
        }
        const float4* src = (const float4*)(cb + (size_t)bi * DIM);
        float4*       dst = (float4*)(out + (size_t)grow * DIM);
#pragma unroll
        for (int i = 0; i < 4; i++) dst[lane + i * 32] = src[lane + i * 32];
    }

    // per-CTA loss partial
    if (lane == 0) lsum[wid] = wsum;
    __syncthreads();
    if (tid == 0) {
        float s = 0.f;
#pragma unroll
        for (int w = 0; w < 8; w++) s += lsum[w];
        g_partial[blk] = s;
    }
}

// ---------------------------------------------------------------------------
// Kernel 2: final deterministic loss reduction over 148 CTA partials
// ---------------------------------------------------------------------------
__global__ void vq_loss_kernel(float* __restrict__ out) {
    __shared__ float s[256];
    int t = threadIdx.x;
    s[t] = (t < NCTA) ? g_partial[t] : 0.f;
    __syncthreads();
#pragma unroll
    for (int o = 128; o > 0; o >>= 1) {
        if (t < o) s[t] += s[t + o];
        __syncthreads();
    }
    if (t == 0) {
        out[COMMIT_OFF] = s[0];
        out[LOSS_OFF]   = 1.25f * s[0];
    }
}

// ---------------------------------------------------------------------------
extern "C" void kernel_launch(void* const* d_in, const int* in_sizes, int n_in,
                              void* d_out, int out_size) {
    const float* x  = (const float*)d_in[0];   // [16384, 512]
    const float* cb = (const float*)d_in[1];   // [8192, 512]
    float* out = (float*)d_out;

    cudaFuncSetAttribute(vq_mma_kernel,
                         cudaFuncAttributeMaxDynamicSharedMemorySize, SMEM_DYN);

    split_cb_kernel<<<NCODE / 16, 512>>>(cb);
    vq_mma_kernel<<<NCTA, 256, SMEM_DYN>>>(x, cb, out);
    vq_loss_kernel<<<1, 256>>>(out);
}